// round 1
// baseline (speedup 1.0000x reference)
#include <cuda_runtime.h>

// ---------------- problem constants ----------------
#define NCLS 16
#define NSUP 25
#define CWH  3072
#define DF   640
#define MS   400      // N_c * N_S
#define MQ   240      // N_c * N_Q
#define MKF  640      // MS + MQ (stacked feature GEMM rows)
#define NRHS 16
#define NCAT 416      // 400 + 16 (fused squaring + X update)
#define SPLITS 4

// ---------------- device scratch (no allocation allowed) ----------------
__device__ __align__(16) float g_KF[MKF * DF];               // rows 0..399 = K, 400..639 = f_x
__device__ __align__(16) float g_parts[SPLITS * MKF * DF];   // split-K partials (max usage)
__device__ __align__(16) float g_aul[MS * MS];
__device__ __align__(16) float g_A2[MS * MS];
__device__ __align__(16) float g_Ba[MS * MS];
__device__ __align__(16) float g_Bb[MS * MS];
__device__ __align__(16) float g_Xa[MS * NRHS];
__device__ __align__(16) float g_Xb[MS * NRHS];
__device__ __align__(16) float g_red[256];
__device__ __align__(16) float g_scal[4];                    // [0]=b, [1]=1/b
__device__ __align__(16) float g_w[NRHS * DF];

// ============================================================
// GEMM 1: KF = [S_flat; Q_flat] @ W_base   (640 x 3072 x 640)
// BM=128 BN=64 BK=16, 128 threads, 8x8 micro-tile, split-K partials
// ============================================================
__global__ __launch_bounds__(128) void k_gemm_kf(const float* __restrict__ S,
                                                 const float* __restrict__ Qm,
                                                 const float* __restrict__ W) {
    __shared__ float As[16][132];
    __shared__ float Bs[16][68];
    const int tid = threadIdx.x;
    const int n0 = blockIdx.x * 64;
    const int m0 = blockIdx.y * 128;
    const int sp = blockIdx.z;
    const int nkt = CWH / 16;
    const int kt0 = sp * nkt / SPLITS, kt1 = (sp + 1) * nkt / SPLITS;
    const int arow = m0 + tid;  // < 640 always
    const float* Ap = (arow < MS) ? (S + (size_t)arow * CWH)
                                  : (Qm + (size_t)(arow - MS) * CWH);
    const int ty = tid >> 3, tx = tid & 7;
    float acc[8][8];
#pragma unroll
    for (int i = 0; i < 8; i++)
#pragma unroll
        for (int j = 0; j < 8; j++) acc[i][j] = 0.f;

    for (int kt = kt0; kt < kt1; ++kt) {
        const int k0 = kt * 16;
#pragma unroll
        for (int q = 0; q < 4; q++) {
            float4 v = *reinterpret_cast<const float4*>(Ap + k0 + q * 4);
            As[q * 4 + 0][tid] = v.x; As[q * 4 + 1][tid] = v.y;
            As[q * 4 + 2][tid] = v.z; As[q * 4 + 3][tid] = v.w;
        }
#pragma unroll
        for (int i = 0; i < 2; i++) {
            int idx = tid + i * 128;
            int kk = idx >> 4, c4 = idx & 15;
            float4 v = *reinterpret_cast<const float4*>(W + (size_t)(k0 + kk) * DF + n0 + c4 * 4);
            *reinterpret_cast<float4*>(&Bs[kk][c4 * 4]) = v;
        }
        __syncthreads();
#pragma unroll
        for (int k = 0; k < 16; k++) {
            float a[8], b[8];
            *(float4*)&a[0] = *(float4*)&As[k][ty * 8];
            *(float4*)&a[4] = *(float4*)&As[k][ty * 8 + 4];
            *(float4*)&b[0] = *(float4*)&Bs[k][tx * 8];
            *(float4*)&b[4] = *(float4*)&Bs[k][tx * 8 + 4];
#pragma unroll
            for (int i = 0; i < 8; i++)
#pragma unroll
                for (int j = 0; j < 8; j++) acc[i][j] = fmaf(a[i], b[j], acc[i][j]);
        }
        __syncthreads();
    }
    float* out = g_parts + (size_t)sp * MKF * DF;
#pragma unroll
    for (int i = 0; i < 8; i++) {
        int r = m0 + ty * 8 + i;
#pragma unroll
        for (int j = 0; j < 8; j += 4) {
            float4 v = make_float4(acc[i][j], acc[i][j + 1], acc[i][j + 2], acc[i][j + 3]);
            *reinterpret_cast<float4*>(out + (size_t)r * DF + n0 + tx * 8 + j) = v;
        }
    }
}

__global__ void k_reduce_kf() {
    int i = blockIdx.x * 256 + threadIdx.x;
    if (i >= MKF * DF) return;
    const size_t T = (size_t)MKF * DF;
    g_KF[i] = g_parts[i] + g_parts[T + i] + g_parts[2 * T + i] + g_parts[3 * T + i];
}

// ============================================================
// GEMM 2 (NT): aul = K @ K^T (+50 I in reduce)   400 x 400 x 640
// ============================================================
__global__ __launch_bounds__(128) void k_gemm_aul() {
    __shared__ float As[16][132];
    __shared__ float Bs[16][68];
    const int tid = threadIdx.x;
    const int n0 = blockIdx.x * 64;
    const int m0 = blockIdx.y * 128;
    const int sp = blockIdx.z;
    const int nkt = DF / 16;  // 40
    const int kt0 = sp * nkt / SPLITS, kt1 = (sp + 1) * nkt / SPLITS;
    const int arow = m0 + tid;  // up to 511 < 640: safe reads, garbage rows store-guarded
    const float* Ap = g_KF + (size_t)arow * DF;
    const int ty = tid >> 3, tx = tid & 7;
    float acc[8][8];
#pragma unroll
    for (int i = 0; i < 8; i++)
#pragma unroll
        for (int j = 0; j < 8; j++) acc[i][j] = 0.f;

    for (int kt = kt0; kt < kt1; ++kt) {
        const int k0 = kt * 16;
#pragma unroll
        for (int q = 0; q < 4; q++) {
            float4 v = *reinterpret_cast<const float4*>(Ap + k0 + q * 4);
            As[q * 4 + 0][tid] = v.x; As[q * 4 + 1][tid] = v.y;
            As[q * 4 + 2][tid] = v.z; As[q * 4 + 3][tid] = v.w;
        }
#pragma unroll
        for (int i = 0; i < 2; i++) {
            int idx = tid + i * 128;          // 0..255
            int n = idx >> 2, q = idx & 3;    // n: 0..63
            float4 v = *reinterpret_cast<const float4*>(g_KF + (size_t)(n0 + n) * DF + k0 + q * 4);
            Bs[q * 4 + 0][n] = v.x; Bs[q * 4 + 1][n] = v.y;
            Bs[q * 4 + 2][n] = v.z; Bs[q * 4 + 3][n] = v.w;
        }
        __syncthreads();
#pragma unroll
        for (int k = 0; k < 16; k++) {
            float a[8], b[8];
            *(float4*)&a[0] = *(float4*)&As[k][ty * 8];
            *(float4*)&a[4] = *(float4*)&As[k][ty * 8 + 4];
            *(float4*)&b[0] = *(float4*)&Bs[k][tx * 8];
            *(float4*)&b[4] = *(float4*)&Bs[k][tx * 8 + 4];
#pragma unroll
            for (int i = 0; i < 8; i++)
#pragma unroll
                for (int j = 0; j < 8; j++) acc[i][j] = fmaf(a[i], b[j], acc[i][j]);
        }
        __syncthreads();
    }
    float* out = g_parts + (size_t)sp * MS * MS;
#pragma unroll
    for (int i = 0; i < 8; i++) {
        int r = m0 + ty * 8 + i;
        if (r >= MS) continue;
#pragma unroll
        for (int j = 0; j < 8; j++) {
            int c = n0 + tx * 8 + j;
            if (c < MS) out[(size_t)r * MS + c] = acc[i][j];
        }
    }
}

__global__ void k_reduce_aul() {
    int i = blockIdx.x * 256 + threadIdx.x;
    if (i >= MS * MS) return;
    const size_t T = (size_t)MS * MS;
    float s = g_parts[i] + g_parts[T + i] + g_parts[2 * T + i] + g_parts[3 * T + i];
    int r = i / MS, c = i - r * MS;
    if (r == c) s += 50.0f;
    g_aul[i] = s;
}

// ============================================================
// GEMM 3 (NN): A2 = aul @ aul   400 x 400 x 400
// ============================================================
__global__ __launch_bounds__(128) void k_gemm_a2() {
    __shared__ float As[16][132];
    __shared__ float Bs[16][68];
    const int tid = threadIdx.x;
    const int n0 = blockIdx.x * 64;
    const int m0 = blockIdx.y * 128;
    const int sp = blockIdx.z;
    const int nkt = MS / 16;  // 25
    const int kt0 = sp * nkt / SPLITS, kt1 = (sp + 1) * nkt / SPLITS;
    int arow = m0 + tid; if (arow >= MS) arow = MS - 1;  // clamp: garbage rows store-guarded
    const float* Ap = g_aul + (size_t)arow * MS;
    const int ty = tid >> 3, tx = tid & 7;
    float acc[8][8];
#pragma unroll
    for (int i = 0; i < 8; i++)
#pragma unroll
        for (int j = 0; j < 8; j++) acc[i][j] = 0.f;

    for (int kt = kt0; kt < kt1; ++kt) {
        const int k0 = kt * 16;
#pragma unroll
        for (int q = 0; q < 4; q++) {
            float4 v = *reinterpret_cast<const float4*>(Ap + k0 + q * 4);
            As[q * 4 + 0][tid] = v.x; As[q * 4 + 1][tid] = v.y;
            As[q * 4 + 2][tid] = v.z; As[q * 4 + 3][tid] = v.w;
        }
#pragma unroll
        for (int i = 0; i < 2; i++) {
            int idx = tid + i * 128;
            int kk = idx >> 4, c4 = idx & 15;
            int c = n0 + c4 * 4;
            float4 v = make_float4(0.f, 0.f, 0.f, 0.f);
            if (c < MS) v = *reinterpret_cast<const float4*>(g_aul + (size_t)(k0 + kk) * MS + c);
            *reinterpret_cast<float4*>(&Bs[kk][c4 * 4]) = v;
        }
        __syncthreads();
#pragma unroll
        for (int k = 0; k < 16; k++) {
            float a[8], b[8];
            *(float4*)&a[0] = *(float4*)&As[k][ty * 8];
            *(float4*)&a[4] = *(float4*)&As[k][ty * 8 + 4];
            *(float4*)&b[0] = *(float4*)&Bs[k][tx * 8];
            *(float4*)&b[4] = *(float4*)&Bs[k][tx * 8 + 4];
#pragma unroll
            for (int i = 0; i < 8; i++)
#pragma unroll
                for (int j = 0; j < 8; j++) acc[i][j] = fmaf(a[i], b[j], acc[i][j]);
        }
        __syncthreads();
    }
    float* out = g_parts + (size_t)sp * MS * MS;
#pragma unroll
    for (int i = 0; i < 8; i++) {
        int r = m0 + ty * 8 + i;
        if (r >= MS) continue;
#pragma unroll
        for (int j = 0; j < 8; j++) {
            int c = n0 + tx * 8 + j;
            if (c < MS) out[(size_t)r * MS + c] = acc[i][j];
        }
    }
}

__global__ void k_reduce_a2() {
    int i = blockIdx.x * 256 + threadIdx.x;
    if (i >= MS * MS) return;
    const size_t T = (size_t)MS * MS;
    g_A2[i] = g_parts[i] + g_parts[T + i] + g_parts[2 * T + i] + g_parts[3 * T + i];
}

// ============================================================
// Spectral bound: b = ||A2||_F^(1/2) >= lambda_max(aul)  (deterministic reduce)
// ============================================================
__global__ void k_f2_part() {
    __shared__ float sh[256];
    const int TOT = MS * MS;                 // 160000
    const int CH = (TOT + 255) / 256;        // 625 per block
    int base = blockIdx.x * CH;
    int hi = base + CH; if (hi > TOT) hi = TOT;
    float s = 0.f;
    for (int i = base + threadIdx.x; i < hi; i += 256) { float v = g_A2[i]; s += v * v; }
    sh[threadIdx.x] = s; __syncthreads();
    for (int o = 128; o > 0; o >>= 1) {
        if (threadIdx.x < o) sh[threadIdx.x] += sh[threadIdx.x + o];
        __syncthreads();
    }
    if (threadIdx.x == 0) g_red[blockIdx.x] = sh[0];
}

__global__ void k_f2_final() {
    __shared__ float sh[256];
    sh[threadIdx.x] = g_red[threadIdx.x]; __syncthreads();
    for (int o = 128; o > 0; o >>= 1) {
        if (threadIdx.x < o) sh[threadIdx.x] += sh[threadIdx.x + o];
        __syncthreads();
    }
    if (threadIdx.x == 0) {
        float b = sqrtf(sqrtf(sh[0])) * 1.0001f;
        if (!(b > 51.f)) b = 51.f;
        g_scal[0] = b;
        g_scal[1] = 1.0f / b;
    }
}

// B = I - A/b ; B^2 = I - 2A/b + A2/b^2  (both closed-form, saves one GEMM)
__global__ void k_build_B() {
    int i = blockIdx.x * 256 + threadIdx.x;
    if (i >= MS * MS) return;
    float ib = g_scal[1];
    int r = i / MS, c = i - r * MS;
    float a = g_aul[i] * ib;
    float a2 = g_A2[i] * ib * ib;
    float d = (r == c) ? 1.f : 0.f;
    g_Ba[i] = d - a;               // B
    g_Bb[i] = d - 2.f * a + a2;    // B^2
}

// X1 = (I + B) P ; P[j][c] = (j/25 == c). (BP)[j][c] = sum of 25 B entries.
__global__ void k_build_X1() {
    int idx = blockIdx.x * 256 + threadIdx.x;
    if (idx >= MS * NRHS) return;
    int j = idx >> 4, c = idx & 15;
    float s = ((j / NSUP) == c) ? 1.f : 0.f;
    const float* row = g_Ba + (size_t)j * MS + c * NSUP;
#pragma unroll
    for (int t = 0; t < NSUP; t++) s += row[t];
    g_Xa[idx] = s;
}

// ============================================================
// Fused iteration: [Bnext | Xdelta] = Bcur @ [Bcur | X]   400 x 416 x 400
// sel=1: A=g_Bb, X=g_Xa ; sel=0: A=g_Ba, X=g_Xb
// ============================================================
__global__ __launch_bounds__(128) void k_gemm_iter(int sel) {
    const float* Bcur = sel ? g_Bb : g_Ba;
    const float* Xin = sel ? g_Xa : g_Xb;
    __shared__ float As[16][132];
    __shared__ float Bs[16][68];
    const int tid = threadIdx.x;
    const int n0 = blockIdx.x * 64;
    const int m0 = blockIdx.y * 128;
    const int sp = blockIdx.z;
    const int nkt = MS / 16;  // 25
    const int kt0 = sp * nkt / SPLITS, kt1 = (sp + 1) * nkt / SPLITS;
    int arow = m0 + tid; if (arow >= MS) arow = MS - 1;
    const float* Ap = Bcur + (size_t)arow * MS;
    const int ty = tid >> 3, tx = tid & 7;
    float acc[8][8];
#pragma unroll
    for (int i = 0; i < 8; i++)
#pragma unroll
        for (int j = 0; j < 8; j++) acc[i][j] = 0.f;

    for (int kt = kt0; kt < kt1; ++kt) {
        const int k0 = kt * 16;
#pragma unroll
        for (int q = 0; q < 4; q++) {
            float4 v = *reinterpret_cast<const float4*>(Ap + k0 + q * 4);
            As[q * 4 + 0][tid] = v.x; As[q * 4 + 1][tid] = v.y;
            As[q * 4 + 2][tid] = v.z; As[q * 4 + 3][tid] = v.w;
        }
#pragma unroll
        for (int i = 0; i < 2; i++) {
            int idx = tid + i * 128;
            int kk = idx >> 4, c4 = idx & 15;
            int c = n0 + c4 * 4;
            int kr = k0 + kk;
            float4 v = make_float4(0.f, 0.f, 0.f, 0.f);
            if (c < MS) v = *reinterpret_cast<const float4*>(Bcur + (size_t)kr * MS + c);
            else if (c < NCAT) v = *reinterpret_cast<const float4*>(Xin + (size_t)kr * NRHS + (c - MS));
            *reinterpret_cast<float4*>(&Bs[kk][c4 * 4]) = v;
        }
        __syncthreads();
#pragma unroll
        for (int k = 0; k < 16; k++) {
            float a[8], b[8];
            *(float4*)&a[0] = *(float4*)&As[k][ty * 8];
            *(float4*)&a[4] = *(float4*)&As[k][ty * 8 + 4];
            *(float4*)&b[0] = *(float4*)&Bs[k][tx * 8];
            *(float4*)&b[4] = *(float4*)&Bs[k][tx * 8 + 4];
#pragma unroll
            for (int i = 0; i < 8; i++)
#pragma unroll
                for (int j = 0; j < 8; j++) acc[i][j] = fmaf(a[i], b[j], acc[i][j]);
        }
        __syncthreads();
    }
    float* out = g_parts + (size_t)sp * MS * NCAT;
#pragma unroll
    for (int i = 0; i < 8; i++) {
        int r = m0 + ty * 8 + i;
        if (r >= MS) continue;
#pragma unroll
        for (int j = 0; j < 8; j++) {
            int c = n0 + tx * 8 + j;
            if (c < NCAT) out[(size_t)r * NCAT + c] = acc[i][j];
        }
    }
}

__global__ void k_reduce_iter(int sel) {
    int i = blockIdx.x * 256 + threadIdx.x;
    const int TOT = MS * NCAT;
    if (i >= TOT) return;
    float s = g_parts[i] + g_parts[TOT + i] + g_parts[2 * TOT + i] + g_parts[3 * TOT + i];
    int r = i / NCAT, c = i - r * NCAT;
    if (c < MS) {
        (sel ? g_Ba : g_Bb)[(size_t)r * MS + c] = s;           // Bnext = Bcur^2
    } else {
        const float* Xin = sel ? g_Xa : g_Xb;
        float* Xout = sel ? g_Xb : g_Xa;
        int xc = c - MS;
        Xout[r * NRHS + xc] = Xin[r * NRHS + xc] + s;           // X += Bcur X
    }
}

// Final factor (j=11): X_final = Xa + B^{2048} @ Xa  (B^{2048} lives in g_Bb)
__global__ void k_xonly() {
    int idx = blockIdx.x * blockDim.x + threadIdx.x;
    if (idx >= MS * NRHS) return;
    int j = idx >> 4, c = idx & 15;
    const float* br = g_Bb + (size_t)j * MS;
    float s = g_Xa[idx];
    for (int k = 0; k < MS; k++) s = fmaf(br[k], g_Xa[k * NRHS + c], s);
    g_Xb[idx] = s;
}

// w[c][d] = (1/b) * sum_j X[j][c] * K[j][d]
__global__ void k_w() {
    int idx = blockIdx.x * 256 + threadIdx.x;
    if (idx >= NRHS * DF) return;
    int c = idx / DF, d = idx - c * DF;
    float s = 0.f;
    for (int j = 0; j < MS; j++) s = fmaf(g_Xb[j * NRHS + c], g_KF[(size_t)j * DF + d], s);
    g_w[idx] = s * g_scal[1];
}

// logits[q][c] = -gamma * sum_d f_x[q][d] * w[c][d]
__global__ void k_logits(float* __restrict__ out, const float* __restrict__ gamma) {
    int idx = blockIdx.x * 256 + threadIdx.x;
    if (idx >= MQ * NCLS) return;
    int q = idx >> 4, c = idx & 15;
    const float4* f = reinterpret_cast<const float4*>(g_KF + (size_t)(MS + q) * DF);
    const float4* wr = reinterpret_cast<const float4*>(g_w + (size_t)c * DF);
    float s = 0.f;
    for (int d = 0; d < DF / 4; d++) {
        float4 a = f[d], b = wr[d];
        s = fmaf(a.x, b.x, s); s = fmaf(a.y, b.y, s);
        s = fmaf(a.z, b.z, s); s = fmaf(a.w, b.w, s);
    }
    out[idx] = -gamma[0] * s;
}

// ============================================================
extern "C" void kernel_launch(void* const* d_in, const int* in_sizes, int n_in,
                              void* d_out, int out_size) {
    const float* S = (const float*)d_in[0];
    const float* Qm = (const float*)d_in[1];
    const float* W = (const float*)d_in[2];
    const float* gamma = (const float*)d_in[3];
    float* out = (float*)d_out;
    (void)in_sizes; (void)n_in; (void)out_size;

    dim3 thr(128);
    // 1) features: KF = [S;Q] @ W_base
    k_gemm_kf<<<dim3(DF / 64, MKF / 128, SPLITS), thr>>>(S, Qm, W);
    k_reduce_kf<<<(MKF * DF + 255) / 256, 256>>>();
    // 2) aul = K K^T + 50 I
    k_gemm_aul<<<dim3(7, 4, SPLITS), thr>>>();
    k_reduce_aul<<<(MS * MS + 255) / 256, 256>>>();
    // 3) A2 = aul^2 (for spectral bound AND free B^2)
    k_gemm_a2<<<dim3(7, 4, SPLITS), thr>>>();
    k_reduce_a2<<<(MS * MS + 255) / 256, 256>>>();
    // 4) b = ||A2||_F^(1/2) >= lambda_max
    k_f2_part<<<256, 256>>>();
    k_f2_final<<<1, 256>>>();
    // 5) B, B^2, X1 = (I+B)P
    k_build_B<<<(MS * MS + 255) / 256, 256>>>();
    k_build_X1<<<(MS * NRHS + 255) / 256, 256>>>();
    // 6) log-depth Neumann: factors j=1..10 fused (X update + squaring)
    int sel = 1;
    for (int j = 1; j <= 10; j++) {
        k_gemm_iter<<<dim3(7, 4, SPLITS), thr>>>(sel);
        k_reduce_iter<<<(MS * NCAT + 255) / 256, 256>>>(sel);
        sel ^= 1;
    }
    // 7) factor j=11 (X only), solution Z = Xb / b
    k_xonly<<<(MS * NRHS + 255) / 256, 256>>>();
    // 8) w = Z^T K ; logits = -gamma * f_x w^T
    k_w<<<(NRHS * DF + 255) / 256, 256>>>();
    k_logits<<<(MQ * NCLS + 255) / 256, 256>>>(out, gamma);
}